// round 10
// baseline (speedup 1.0000x reference)
#include <cuda_runtime.h>
#include <math.h>

#define EPSV 1e-5f

static const int BATCH = 4;
static const int CCH   = 512;
static const int NSP   = 4096;   // H*W

// ---------------- scratch (device globals; no runtime allocation) ----------------
__device__ float g_xn [(size_t)4 * 512 * 4096];
__device__ float g_q  [(size_t)4 * 512 * 4096];
__device__ float g_k  [(size_t)4 * 512 * 4096];
__device__ float g_v  [(size_t)4 * 512 * 4096];
__device__ float g_o  [(size_t)4 * 512 * 4096];   // also split-K partials [4][8][512][512]
__device__ float g_cf [(size_t)4 * 512 * 4096];
__device__ float g_sf [(size_t)4 * 512 * 4096];
__device__ float g_attn[(size_t)4 * 4096 * 4096];

// ---------------- helpers ----------------
__device__ __forceinline__ unsigned f2tf(float x) {
    unsigned u;
    asm("cvt.rna.tf32.f32 %0, %1;" : "=r"(u) : "f"(x));
    return u;
}
__device__ __forceinline__ float rndtf(float x) { return __uint_as_float(f2tf(x)); }

__device__ __forceinline__ void mma8(float* c, const unsigned* a, const unsigned* b) {
    asm volatile(
        "mma.sync.aligned.m16n8k8.row.col.f32.tf32.tf32.f32 "
        "{%0,%1,%2,%3}, {%4,%5,%6,%7}, {%8,%9}, {%0,%1,%2,%3};"
        : "+f"(c[0]), "+f"(c[1]), "+f"(c[2]), "+f"(c[3])
        : "r"(a[0]), "r"(a[1]), "r"(a[2]), "r"(a[3]), "r"(b[0]), "r"(b[1]));
}
__device__ __forceinline__ void cpasync4(unsigned dst, const float* src) {
    asm volatile("cp.async.ca.shared.global [%0], [%1], 4;" :: "r"(dst), "l"(src));
}
#define CP_COMMIT() asm volatile("cp.async.commit_group;" ::: "memory")
#define CP_WAIT0()  asm volatile("cp.async.wait_group 0;"  ::: "memory")

// ---------------- MVN: per-row mean/var normalize (unbiased var, ddof=1) ----------------
__global__ void mvn_kernel(const float* __restrict__ x, float* __restrict__ y, int n) {
    const float* xr = x + (size_t)blockIdx.x * n;
    float*       yr = y + (size_t)blockIdx.x * n;
    int tid = threadIdx.x;
    float s = 0.f, s2 = 0.f;
    for (int i = tid; i < n; i += blockDim.x) {
        float v = xr[i];
        s += v; s2 += v * v;
    }
    __shared__ float sh0[256];
    __shared__ float sh1[256];
    sh0[tid] = s; sh1[tid] = s2;
    __syncthreads();
    for (int o = 128; o > 0; o >>= 1) {
        if (tid < o) { sh0[tid] += sh0[tid + o]; sh1[tid] += sh1[tid + o]; }
        __syncthreads();
    }
    float mean = sh0[0] / (float)n;
    float var  = (sh1[0] - (float)n * mean * mean) / (float)(n - 1);
    float inv  = rsqrtf(var + EPSV);
    for (int i = tid; i < n; i += blockDim.x) {
        yr[i] = (xr[i] - mean) * inv;
    }
}

// ---------------- row softmax (in place), outputs tf32-rounded ----------------
__global__ void softmax_kernel(float* __restrict__ data, int n) {
    float* r = data + (size_t)blockIdx.x * n;
    int tid = threadIdx.x;
    int per = n / blockDim.x;       // 16 (spatial) or 2 (channel)
    float buf[16];
    __shared__ float sh[256];

    float m = -1e30f;
#pragma unroll 16
    for (int i = 0; i < 16; i++) {
        if (i < per) {
            float v = r[tid + i * blockDim.x];
            buf[i] = v;
            m = fmaxf(m, v);
        }
    }
    sh[tid] = m; __syncthreads();
    for (int o = 128; o > 0; o >>= 1) {
        if (tid < o) sh[tid] = fmaxf(sh[tid], sh[tid + o]);
        __syncthreads();
    }
    float mx = sh[0];
    __syncthreads();

    float s = 0.f;
#pragma unroll 16
    for (int i = 0; i < 16; i++) {
        if (i < per) {
            float e = __expf(buf[i] - mx);
            buf[i] = e;
            s += e;
        }
    }
    sh[tid] = s; __syncthreads();
    for (int o = 128; o > 0; o >>= 1) {
        if (tid < o) sh[tid] += sh[tid + o];
        __syncthreads();
    }
    float inv = 1.f / sh[0];
#pragma unroll 16
    for (int i = 0; i < 16; i++) {
        if (i < per) r[tid + i * blockDim.x] = rndtf(buf[i] * inv);
    }
}

// ---------------- split-K partial reduction: out[b][i] = sum_kc part[b*8+kc][i] ----------------
__global__ void reduce8_kernel(const float* __restrict__ part, float* __restrict__ out) {
    const long long WWv = (long long)512 * 512 / 4;
    long long gid = (long long)blockIdx.x * blockDim.x + threadIdx.x;
    long long b = gid / WWv, i = gid % WWv;
    const float4* p = (const float4*)part + b * 8 * WWv + i;
    float4 a = p[0];
#pragma unroll
    for (int kc = 1; kc < 8; kc++) {
        float4 v = p[(long long)kc * WWv];
        a.x += v.x; a.y += v.y; a.z += v.z; a.w += v.w;
    }
    ((float4*)out)[b * WWv + i] = a;
}

#define RS 132   // row stride in float2 units (128 + 4 pad)

// ---------------- r9-proven TF32 GEMM (cvt staging) + rnd epilogue flag ----------------
__global__ __launch_bounds__(256) void gemm_tc(
    const float* __restrict__ A, const float* __restrict__ Bp, float* __restrict__ C,
    long long aBatch, long long sam, long long sak,
    long long bBatch, long long sbk, long long sbn,
    long long cBatch,
    const float* __restrict__ bias,
    const float* __restrict__ res, long long rBatch,
    int M, int N, int K, int rnd)
{
    const int BM = 128, BK = 16;
    __shared__ float2 As2[8][RS];
    __shared__ float2 Bs2[8][RS];

    int bz = blockIdx.z;
    A  += (long long)bz * aBatch;
    Bp += (long long)bz * bBatch;
    C  += (long long)bz * cBatch;
    if (res) res += (long long)bz * rBatch;

    int tid  = threadIdx.x;
    int lane = tid & 31;
    int warp = tid >> 5;
    int m0 = blockIdx.y * BM;
    int n0 = blockIdx.x * BM;
    int wm = (warp & 1) * 64;
    int wn = (warp >> 1) * 32;

    bool aK = (sak == 1);
    bool bK = (sbk == 1);

    int a_kk, a_mm; long long aOff, aStep;
    if (aK) { a_kk = tid & 15; a_mm = tid >> 4;
              aOff = (long long)(m0 + a_mm) * sam + a_kk; aStep = 16 * sam; }
    else    { a_mm = tid & 127; a_kk = tid >> 7;
              aOff = (long long)(m0 + a_mm) * sam + (long long)a_kk * sak; aStep = 2 * sak; }
    int b_kk, b_nn; long long bOff, bStep;
    if (bK) { b_kk = tid & 15; b_nn = tid >> 4;
              bOff = (long long)(n0 + b_nn) * sbn + b_kk; bStep = 16 * sbn; }
    else    { b_nn = tid & 127; b_kk = tid >> 7;
              bOff = (long long)(n0 + b_nn) * sbn + (long long)b_kk * sbk; bStep = 2 * sbk; }

    int ap = ((a_kk >> 3) << 2) | (a_kk & 3);
    int ah = (a_kk >> 2) & 1;
    int bp = ((b_kk >> 3) << 2) | (b_kk & 3);
    int bh = (b_kk >> 2) & 1;

    int r = lane >> 2;
    const unsigned aIdx = (unsigned)((lane & 3) * RS + wm + r);
    const unsigned bIdx = (unsigned)((lane & 3) * RS + wn + r);
    const float2* a2p = &As2[0][0];
    const float2* b2p = &Bs2[0][0];

    float acc[4][4][4];
#pragma unroll
    for (int mt = 0; mt < 4; mt++)
#pragma unroll
        for (int nt = 0; nt < 4; nt++)
#pragma unroll
            for (int i = 0; i < 4; i++) acc[mt][nt][i] = 0.f;

    float ra[8], rb[8];
#pragma unroll
    for (int i = 0; i < 8; i++) ra[i] = A[aOff + i * aStep];
#pragma unroll
    for (int i = 0; i < 8; i++) rb[i] = Bp[bOff + i * bStep];

    for (int k0 = 0; k0 < K; k0 += BK) {
        if (aK) {
            unsigned* dst = (unsigned*)&As2[ap][a_mm] + ah;
#pragma unroll
            for (int i = 0; i < 8; i++) dst[32 * i] = f2tf(ra[i]);
        } else {
#pragma unroll
            for (int i = 0; i < 8; i++) {
                int k = a_kk + 2 * i;
                int p = ((k >> 3) << 2) | (k & 3);
                int h = (k >> 2) & 1;
                ((unsigned*)&As2[p][a_mm])[h] = f2tf(ra[i]);
            }
        }
        if (bK) {
            unsigned* dst = (unsigned*)&Bs2[bp][b_nn] + bh;
#pragma unroll
            for (int i = 0; i < 8; i++) dst[32 * i] = f2tf(rb[i]);
        } else {
#pragma unroll
            for (int i = 0; i < 8; i++) {
                int k = b_kk + 2 * i;
                int p = ((k >> 3) << 2) | (k & 3);
                int h = (k >> 2) & 1;
                ((unsigned*)&Bs2[p][b_nn])[h] = f2tf(rb[i]);
            }
        }
        __syncthreads();

        aOff += (long long)BK * sak;
        bOff += (long long)BK * sbk;
        if (k0 + BK < K) {
#pragma unroll
            for (int i = 0; i < 8; i++) ra[i] = A[aOff + i * aStep];
#pragma unroll
            for (int i = 0; i < 8; i++) rb[i] = Bp[bOff + i * bStep];
        }

#pragma unroll
        for (int ks = 0; ks < 2; ks++) {
            const unsigned off = ks * (4u * RS);
            unsigned af[4][4], bf[4][2];
#pragma unroll
            for (int mt = 0; mt < 4; mt++) {
                float2 lo = a2p[aIdx + off + mt * 16];
                float2 hi = a2p[aIdx + off + mt * 16 + 8];
                af[mt][0] = __float_as_uint(lo.x);
                af[mt][1] = __float_as_uint(hi.x);
                af[mt][2] = __float_as_uint(lo.y);
                af[mt][3] = __float_as_uint(hi.y);
            }
#pragma unroll
            for (int nt = 0; nt < 4; nt++) {
                float2 pb = b2p[bIdx + off + nt * 8];
                bf[nt][0] = __float_as_uint(pb.x);
                bf[nt][1] = __float_as_uint(pb.y);
            }
#pragma unroll
            for (int mt = 0; mt < 4; mt++)
#pragma unroll
                for (int nt = 0; nt < 4; nt++)
                    mma8(acc[mt][nt], af[mt], bf[nt]);
        }
        __syncthreads();
    }

#pragma unroll
    for (int mt = 0; mt < 4; mt++) {
        int row = m0 + wm + mt * 16 + (lane >> 2);
        float bi0 = bias ? bias[row]     : 0.f;
        float bi1 = bias ? bias[row + 8] : 0.f;
#pragma unroll
        for (int nt = 0; nt < 4; nt++) {
            int col = n0 + wn + nt * 8 + 2 * (lane & 3);
            float2 v0 = make_float2(acc[mt][nt][0] + bi0, acc[mt][nt][1] + bi0);
            float2 v1 = make_float2(acc[mt][nt][2] + bi1, acc[mt][nt][3] + bi1);
            if (res) {
                float2 r0 = *(const float2*)(res + (long long)row * N + col);
                float2 r1 = *(const float2*)(res + (long long)(row + 8) * N + col);
                v0.x += r0.x; v0.y += r0.y;
                v1.x += r1.x; v1.y += r1.y;
            }
            if (rnd) {
                v0.x = rndtf(v0.x); v0.y = rndtf(v0.y);
                v1.x = rndtf(v1.x); v1.y = rndtf(v1.y);
            }
            *(float2*)(C + (long long)row * N + col)       = v0;
            *(float2*)(C + (long long)(row + 8) * N + col) = v1;
        }
    }
}

// ---------------- cp.async TF32 GEMM: both operands pre-rounded to tf32 ----------------
// Same tile/fragment math; double-buffered smem; 2-stage cp.async pipeline;
// no cvt, no bias/res/rnd. nsplit as in r9.
__global__ __launch_bounds__(256, 2) void gemm_async(
    const float* __restrict__ A, const float* __restrict__ Bp, float* __restrict__ C,
    long long aBatch, long long sam, long long sak,
    long long bBatch, long long sbk, long long sbn,
    long long cBatch,
    int M, int N, int K, int nsplit)
{
    const int BM = 128, BK = 16;
    __shared__ float2 As2[2][8][RS];
    __shared__ float2 Bs2[2][8][RS];

    int bz = blockIdx.z;
    int kc = 0;
    if (nsplit > 1) { kc = bz % nsplit; bz /= nsplit; }
    A  += (long long)bz * aBatch + (long long)kc * K * sak;
    Bp += (long long)bz * bBatch + (long long)kc * K * sbk;
    C  += (long long)(bz * nsplit + kc) * cBatch;

    int tid  = threadIdx.x;
    int lane = tid & 31;
    int warp = tid >> 5;
    int m0 = blockIdx.y * BM;
    int n0 = blockIdx.x * BM;
    int wm = (warp & 1) * 64;
    int wn = (warp >> 1) * 32;

    bool aK = (sak == 1);
    bool bK = (sbk == 1);

    int a_kk, a_mm; long long aOff, aStep;
    if (aK) { a_kk = tid & 15; a_mm = tid >> 4;
              aOff = (long long)(m0 + a_mm) * sam + a_kk; aStep = 16 * sam; }
    else    { a_mm = tid & 127; a_kk = tid >> 7;
              aOff = (long long)(m0 + a_mm) * sam + (long long)a_kk * sak; aStep = 2 * sak; }
    int b_kk, b_nn; long long bOff, bStep;
    if (bK) { b_kk = tid & 15; b_nn = tid >> 4;
              bOff = (long long)(n0 + b_nn) * sbn + b_kk; bStep = 16 * sbn; }
    else    { b_nn = tid & 127; b_kk = tid >> 7;
              bOff = (long long)(n0 + b_nn) * sbn + (long long)b_kk * sbk; bStep = 2 * sbk; }

    // smem byte bases + per-thread dst offsets
    const unsigned sA = (unsigned)__cvta_generic_to_shared(&As2[0][0][0]);
    const unsigned sB = (unsigned)__cvta_generic_to_shared(&Bs2[0][0][0]);
    const unsigned BUFB = 8u * RS * 8u;   // bytes per buffer layer
    int ap = ((a_kk >> 3) << 2) | (a_kk & 3);
    int ah = (a_kk >> 2) & 1;
    int bp = ((b_kk >> 3) << 2) | (b_kk & 3);
    int bh = (b_kk >> 2) & 1;
    const unsigned aD0 = (unsigned)((ap * RS + a_mm) * 8 + ah * 4);  // aK path base
    const unsigned bD0 = (unsigned)((bp * RS + b_nn) * 8 + bh * 4);  // bK path base

    int r = lane >> 2;
    const unsigned aIdx = (unsigned)((lane & 3) * RS + wm + r);
    const unsigned bIdx = (unsigned)((lane & 3) * RS + wn + r);
    const float2* a2p = &As2[0][0][0];
    const float2* b2p = &Bs2[0][0][0];

    float acc[4][4][4];
#pragma unroll
    for (int mt = 0; mt < 4; mt++)
#pragma unroll
        for (int nt = 0; nt < 4; nt++)
#pragma unroll
            for (int i = 0; i < 4; i++) acc[mt][nt][i] = 0.f;

    int nch = K / BK;

    // ---- prologue: stage tile 0 into layer 0 ----
    {
        if (aK) {
#pragma unroll
            for (int i = 0; i < 8; i++) cpasync4(sA + aD0 + 128u * i, A + aOff + i * aStep);
        } else {
#pragma unroll
            for (int i = 0; i < 8; i++) {
                int k = a_kk + 2 * i;
                int p = ((k >> 3) << 2) | (k & 3);
                int h = (k >> 2) & 1;
                cpasync4(sA + (unsigned)((p * RS + a_mm) * 8 + h * 4), A + aOff + i * aStep);
            }
        }
        if (bK) {
#pragma unroll
            for (int i = 0; i < 8; i++) cpasync4(sB + bD0 + 128u * i, Bp + bOff + i * bStep);
        } else {
#pragma unroll
            for (int i = 0; i < 8; i++) {
                int k = b_kk + 2 * i;
                int p = ((k >> 3) << 2) | (k & 3);
                int h = (k >> 2) & 1;
                cpasync4(sB + (unsigned)((p * RS + b_nn) * 8 + h * 4), Bp + bOff + i * bStep);
            }
        }
        CP_COMMIT();
    }

    for (int c = 0; c < nch; c++) {
        CP_WAIT0();
        __syncthreads();          // tile c visible; all warps done reading layer (c+1)&1

        if (c + 1 < nch) {
            unsigned lay = (unsigned)((c + 1) & 1) * BUFB;
            aOff += (long long)BK * sak;
            bOff += (long long)BK * sbk;
            if (aK) {
#pragma unroll
                for (int i = 0; i < 8; i++) cpasync4(sA + lay + aD0 + 128u * i, A + aOff + i * aStep);
            } else {
#pragma unroll
                for (int i = 0; i < 8; i++) {
                    int k = a_kk + 2 * i;
                    int p = ((k >> 3) << 2) | (k & 3);
                    int h = (k >> 2) & 1;
                    cpasync4(sA + lay + (unsigned)((p * RS + a_mm) * 8 + h * 4), A + aOff + i * aStep);
                }
            }
            if (bK) {
#pragma unroll
                for (int i = 0; i < 8; i++) cpasync4(sB + lay + bD0 + 128u * i, Bp + bOff + i * bStep);
            } else {
#pragma unroll
                for (int i = 0; i < 8; i++) {
                    int k = b_kk + 2 * i;
                    int p = ((k >> 3) << 2) | (k & 3);
                    int h = (k >> 2) & 1;
                    cpasync4(sB + lay + (unsigned)((p * RS + b_nn) * 8 + h * 4), Bp + bOff + i * bStep);
                }
            }
            CP_COMMIT();
        }

        // ---- compute tile c from layer c&1 ----
        unsigned bsel = (unsigned)(c & 1) * (8u * RS);
#pragma unroll
        for (int ks = 0; ks < 2; ks++) {
            const unsigned off = bsel + ks * (4u * RS);
            unsigned af[4][4], bf[4][2];
#pragma unroll
            for (int mt = 0; mt < 4; mt++) {
                float2 lo = a2p[aIdx + off + mt * 16];
                float2 hi = a2p[aIdx + off + mt * 16 + 8];
                af[mt][0] = __float_as_uint(lo.x);
                af[mt][1] = __float_as_uint(hi.x);
                af[mt][2] = __float_as_uint(lo.y);
                af[mt][3] = __float_as_uint(hi.y);
            }
#pragma unroll
            for (int nt = 0; nt < 4; nt++) {
                float2 pb = b2p[bIdx + off + nt * 8];
                bf[nt][0] = __float_as_uint(pb.x);
                bf[nt][1] = __float_as_uint(pb.y);
            }
#pragma unroll
            for (int mt = 0; mt < 4; mt++)
#pragma unroll
                for (int nt = 0; nt < 4; nt++)
                    mma8(acc[mt][nt], af[mt], bf[nt]);
        }
    }

    // epilogue: plain float2 stores
#pragma unroll
    for (int mt = 0; mt < 4; mt++) {
        int row = m0 + wm + mt * 16 + (lane >> 2);
#pragma unroll
        for (int nt = 0; nt < 4; nt++) {
            int col = n0 + wn + nt * 8 + 2 * (lane & 3);
            *(float2*)(C + (long long)row * N + col) =
                make_float2(acc[mt][nt][0], acc[mt][nt][1]);
            *(float2*)(C + (long long)(row + 8) * N + col) =
                make_float2(acc[mt][nt][2], acc[mt][nt][3]);
        }
    }
}

// ---------------- orchestration ----------------
extern "C" void kernel_launch(void* const* d_in, const int* in_sizes, int n_in,
                              void* d_out, int out_size) {
    const float* content = (const float*)d_in[0];
    const float* style   = (const float*)d_in[1];
    const float* csa_w   = (const float*)d_in[2];
    const float* csa_b   = (const float*)d_in[3];
    const float* ssa_w   = (const float*)d_in[4];
    const float* ssa_b   = (const float*)d_in[5];
    const float* ca_w    = (const float*)d_in[6];
    const float* ca_b    = (const float*)d_in[7];

    float *xn, *q, *k, *v, *o, *cf, *sf, *attn;
    cudaGetSymbolAddress((void**)&xn,   g_xn);
    cudaGetSymbolAddress((void**)&q,    g_q);
    cudaGetSymbolAddress((void**)&k,    g_k);
    cudaGetSymbolAddress((void**)&v,    g_v);
    cudaGetSymbolAddress((void**)&o,    g_o);
    cudaGetSymbolAddress((void**)&cf,   g_cf);
    cudaGetSymbolAddress((void**)&sf,   g_sf);
    cudaGetSymbolAddress((void**)&attn, g_attn);

    const int B = BATCH, C = CCH, N = NSP;
    const long long CN = (long long)C * N;
    const long long NN = (long long)N * N;
    const long long WW = (long long)C * C;

    dim3 convGrid(N / 128, C / 128, B);          // (32,4,4)
    dim3 enGrid  (N / 128, N / 128, B);          // (32,32,4)
    dim3 chSplitGrid(C / 128, C / 128, B * 8);   // (4,4,32)

    // ================= content self-attention =================
    mvn_kernel<<<B * C, 256>>>(content, xn, N);
    gemm_tc<<<convGrid, 256>>>(csa_w + 0 * WW, xn,      q, 0, C, 1, CN, N, 1, CN, csa_b + 0 * C, nullptr, 0, C, N, C, 1);
    gemm_tc<<<convGrid, 256>>>(csa_w + 1 * WW, xn,      k, 0, C, 1, CN, N, 1, CN, csa_b + 1 * C, nullptr, 0, C, N, C, 1);
    gemm_tc<<<convGrid, 256>>>(csa_w + 2 * WW, content, v, 0, C, 1, CN, N, 1, CN, csa_b + 2 * C, nullptr, 0, C, N, C, 1);
    // E[i,j] = sum_c q[c,i] k[c,j]  (pre-rounded operands -> async)
    gemm_async<<<enGrid, 256>>>(q, k, attn, CN, 1, N, CN, N, 1, NN, N, N, C, 1);
    softmax_kernel<<<B * N, 256>>>(attn, N);
    // O[c,i] = sum_j v[c,j] attn[i,j]
    gemm_async<<<convGrid, 256>>>(v, attn, o, CN, N, 1, NN, 1, N, CN, C, N, N, 1);
    gemm_tc<<<convGrid, 256>>>(csa_w + 3 * WW, o, cf, 0, C, 1, CN, N, 1, CN, csa_b + 3 * C, content, CN, C, N, C, 0);

    // ================= style self-attention (channel attention) =================
    mvn_kernel<<<B * C, 256>>>(style, xn, N);
    gemm_tc<<<convGrid, 256>>>(ssa_w + 0 * WW, style, q, 0, C, 1, CN, N, 1, CN, ssa_b + 0 * C, nullptr, 0, C, N, C, 1); // f
    gemm_tc<<<convGrid, 256>>>(ssa_w + 1 * WW, style, k, 0, C, 1, CN, N, 1, CN, ssa_b + 1 * C, nullptr, 0, C, N, C, 1); // g
    gemm_tc<<<convGrid, 256>>>(ssa_w + 2 * WW, xn,    v, 0, C, 1, CN, N, 1, CN, ssa_b + 2 * C, nullptr, 0, C, N, C, 1); // h
    // E[c,d] = sum_i f[c,i] g[d,i] — split-K x8 partials into g_o, reduce into attn
    gemm_async<<<chSplitGrid, 256>>>(q, k, o, CN, N, 1, CN, 1, N, WW, C, C, N / 8, 8);
    reduce8_kernel<<<(int)(B * WW / 4 / 256), 256>>>(o, attn);
    softmax_kernel<<<B * C, 256>>>(attn, C);
    // O[c,i] = sum_d attn[d,c] h[d,i]
    gemm_async<<<convGrid, 256>>>(attn, v, o, WW, 1, C, CN, N, 1, CN, C, N, C, 1);
    gemm_tc<<<convGrid, 256>>>(ssa_w + 3 * WW, o, sf, 0, C, 1, CN, N, 1, CN, ssa_b + 3 * C, style, CN, C, N, C, 0);

    // ================= cross attention =================
    mvn_kernel<<<B * C, 256>>>(cf, xn, N);
    gemm_tc<<<convGrid, 256>>>(ca_w + 0 * WW, xn, q, 0, C, 1, CN, N, 1, CN, ca_b + 0 * C, nullptr, 0, C, N, C, 1);
    mvn_kernel<<<B * C, 256>>>(sf, xn, N);
    gemm_tc<<<convGrid, 256>>>(ca_w + 1 * WW, xn, k, 0, C, 1, CN, N, 1, CN, ca_b + 1 * C, nullptr, 0, C, N, C, 1);
    gemm_tc<<<convGrid, 256>>>(ca_w + 2 * WW, sf, v, 0, C, 1, CN, N, 1, CN, ca_b + 2 * C, nullptr, 0, C, N, C, 1);
    gemm_async<<<enGrid, 256>>>(q, k, attn, CN, 1, N, CN, N, 1, NN, N, N, C, 1);
    softmax_kernel<<<B * N, 256>>>(attn, N);
    gemm_async<<<convGrid, 256>>>(v, attn, o, CN, N, 1, NN, 1, N, CN, C, N, N, 1);
    gemm_tc<<<convGrid, 256>>>(ca_w + 3 * WW, o, (float*)d_out, 0, C, 1, CN, N, 1, CN, ca_b + 3 * C, cf, CN, C, N, C, 0);
}

// round 11
// speedup vs baseline: 1.4662x; 1.4662x over previous
#include <cuda_runtime.h>
#include <math.h>

#define EPSV 1e-5f

static const int BATCH = 4;
static const int CCH   = 512;
static const int NSP   = 4096;   // H*W

// ---------------- scratch (device globals; no runtime allocation) ----------------
__device__ float g_xn [(size_t)4 * 512 * 4096];
__device__ float g_q  [(size_t)4 * 512 * 4096];
__device__ float g_k  [(size_t)4 * 512 * 4096];
__device__ float g_v  [(size_t)4 * 512 * 4096];
__device__ float g_o  [(size_t)4 * 512 * 4096];   // also split-K partials [4][8][512][512]
__device__ float g_cf [(size_t)4 * 512 * 4096];
__device__ float g_sf [(size_t)4 * 512 * 4096];
__device__ float g_attn[(size_t)4 * 4096 * 4096];

// ---------------- helpers ----------------
// pack two f32 -> f16x2 (lo = first arg of the pair we want in bits[15:0])
__device__ __forceinline__ unsigned pack2h(float lo, float hi) {
    unsigned u;
    asm("cvt.rn.f16x2.f32 %0, %1, %2;" : "=r"(u) : "f"(hi), "f"(lo));
    return u;
}

__device__ __forceinline__ void mma16(float* c, const unsigned* a, const unsigned* b) {
    asm volatile(
        "mma.sync.aligned.m16n8k16.row.col.f32.f16.f16.f32 "
        "{%0,%1,%2,%3}, {%4,%5,%6,%7}, {%8,%9}, {%0,%1,%2,%3};"
        : "+f"(c[0]), "+f"(c[1]), "+f"(c[2]), "+f"(c[3])
        : "r"(a[0]), "r"(a[1]), "r"(a[2]), "r"(a[3]), "r"(b[0]), "r"(b[1]));
}

// ---------------- MVN: per-row mean/var normalize (unbiased var, ddof=1) ----------------
__global__ void mvn_kernel(const float* __restrict__ x, float* __restrict__ y, int n) {
    const float* xr = x + (size_t)blockIdx.x * n;
    float*       yr = y + (size_t)blockIdx.x * n;
    int tid = threadIdx.x;
    float s = 0.f, s2 = 0.f;
    for (int i = tid; i < n; i += blockDim.x) {
        float v = xr[i];
        s += v; s2 += v * v;
    }
    __shared__ float sh0[256];
    __shared__ float sh1[256];
    sh0[tid] = s; sh1[tid] = s2;
    __syncthreads();
    for (int o = 128; o > 0; o >>= 1) {
        if (tid < o) { sh0[tid] += sh0[tid + o]; sh1[tid] += sh1[tid + o]; }
        __syncthreads();
    }
    float mean = sh0[0] / (float)n;
    float var  = (sh1[0] - (float)n * mean * mean) / (float)(n - 1);
    float inv  = rsqrtf(var + EPSV);
    for (int i = tid; i < n; i += blockDim.x) {
        yr[i] = (xr[i] - mean) * inv;
    }
}

// ---------------- row softmax (in place), row cached in registers ----------------
__global__ void softmax_kernel(float* __restrict__ data, int n) {
    float* r = data + (size_t)blockIdx.x * n;
    int tid = threadIdx.x;
    int per = n / blockDim.x;       // 16 (spatial) or 2 (channel)
    float buf[16];
    __shared__ float sh[256];

    float m = -1e30f;
#pragma unroll 16
    for (int i = 0; i < 16; i++) {
        if (i < per) {
            float v = r[tid + i * blockDim.x];
            buf[i] = v;
            m = fmaxf(m, v);
        }
    }
    sh[tid] = m; __syncthreads();
    for (int o = 128; o > 0; o >>= 1) {
        if (tid < o) sh[tid] = fmaxf(sh[tid], sh[tid + o]);
        __syncthreads();
    }
    float mx = sh[0];
    __syncthreads();

    float s = 0.f;
#pragma unroll 16
    for (int i = 0; i < 16; i++) {
        if (i < per) {
            float e = __expf(buf[i] - mx);
            buf[i] = e;
            s += e;
        }
    }
    sh[tid] = s; __syncthreads();
    for (int o = 128; o > 0; o >>= 1) {
        if (tid < o) sh[tid] += sh[tid + o];
        __syncthreads();
    }
    float inv = 1.f / sh[0];
#pragma unroll 16
    for (int i = 0; i < 16; i++) {
        if (i < per) r[tid + i * blockDim.x] = buf[i] * inv;
    }
}

// ---------------- split-K partial reduction: out[b][i] = sum_kc part[b*8+kc][i] ----------------
__global__ void reduce8_kernel(const float* __restrict__ part, float* __restrict__ out) {
    const long long WWv = (long long)512 * 512 / 4;
    long long gid = (long long)blockIdx.x * blockDim.x + threadIdx.x;
    long long b = gid / WWv, i = gid % WWv;
    const float4* p = (const float4*)part + b * 8 * WWv + i;
    float4 a = p[0];
#pragma unroll
    for (int kc = 1; kc < 8; kc++) {
        float4 v = p[(long long)kc * WWv];
        a.x += v.x; a.y += v.y; a.z += v.z; a.w += v.w;
    }
    ((float4*)out)[b * WWv + i] = a;
}

// ---------------- FP16 tensor-core batched GEMM, generic strides ----------------
// C[b][m][n] = sum_k A(m,k)*B(k,n) + bias[m] + res[b][m][n]
// Operands converted f32->f16 during staging; accumulation fp32.
// Smem layout (per operand): As2[c][m] = float2 whose .x holds halfs (k=2c,2c+1)
// and .y holds halfs (k=2c+8,2c+9), c in 0..3 — fragments via LDS.64, same proven
// conflict-free indexing as the tf32 paired-k layout.
// nsplit>1: blockIdx.z = b*nsplit + kc (partial C slabs, no bias/res).
// Requires M%128==0, N%128==0, K%16==0.
#define RS 132   // row stride in float2 units (128 + 4 pad)
__global__ __launch_bounds__(256) void gemm_h(
    const float* __restrict__ A, const float* __restrict__ Bp, float* __restrict__ C,
    long long aBatch, long long sam, long long sak,
    long long bBatch, long long sbk, long long sbn,
    long long cBatch,
    const float* __restrict__ bias,
    const float* __restrict__ res, long long rBatch,
    int M, int N, int K, int nsplit)
{
    const int BM = 128, BK = 16;
    __shared__ float2 As2[4][RS];
    __shared__ float2 Bs2[4][RS];

    int bz = blockIdx.z;
    int kc = 0;
    if (nsplit > 1) { kc = bz % nsplit; bz /= nsplit; }
    A  += (long long)bz * aBatch + (long long)kc * K * sak;
    Bp += (long long)bz * bBatch + (long long)kc * K * sbk;
    C  += (long long)(bz * nsplit + kc) * cBatch;
    if (res) res += (long long)bz * rBatch;

    int tid  = threadIdx.x;
    int lane = tid & 31;
    int warp = tid >> 5;
    int m0 = blockIdx.y * BM;
    int n0 = blockIdx.x * BM;
    int wm = (warp & 1) * 64;   // 2 warps along M
    int wn = (warp >> 1) * 32;  // 4 warps along N

    bool aK = (sak == 1);
    bool bK = (sbk == 1);

    // ---- loader descriptors ----
    // K-contig: thread handles kpair j = tid&7 (k = 2j,2j+1), rows mm+32i (i<4).
    // M-contig: thread handles column m = tid&127, k = kb..kb+7 (kb = (tid>>7)*8).
    int a_j = 0, a_mm = 0, a_m = 0;
    long long aOff;
    if (aK) { a_j = tid & 7; a_mm = tid >> 3;
              aOff = (long long)(m0 + a_mm) * sam + 2 * a_j; }
    else    { a_m = tid & 127;
              aOff = (long long)(m0 + a_m) + (long long)((tid >> 7) * 8) * sak; }
    int b_j = 0, b_nn = 0, b_n = 0;
    long long bOff;
    if (bK) { b_j = tid & 7; b_nn = tid >> 3;
              bOff = (long long)(n0 + b_nn) * sbn + 2 * b_j; }
    else    { b_n = tid & 127;
              bOff = (long long)(n0 + b_n) + (long long)((tid >> 7) * 8) * sbk; }
    int selA = tid >> 7;   // M-contig half-select
    int selB = tid >> 7;

    // fragment read indices (float2 units) — proven layout
    int r = lane >> 2;
    const unsigned aIdx = (unsigned)((lane & 3) * RS + wm + r);
    const unsigned bIdx = (unsigned)((lane & 3) * RS + wn + r);
    const float2* a2p = &As2[0][0];
    const float2* b2p = &Bs2[0][0];

    float acc[4][4][4];
#pragma unroll
    for (int mt = 0; mt < 4; mt++)
#pragma unroll
        for (int nt = 0; nt < 4; nt++)
#pragma unroll
            for (int i = 0; i < 4; i++) acc[mt][nt][i] = 0.f;

    // register prefetch of tile 0
    float2 pa2[4], pb2[4];
    float  pa[8],  pb[8];
    if (aK) {
#pragma unroll
        for (int i = 0; i < 4; i++) pa2[i] = *(const float2*)(A + aOff + (long long)(32 * i) * sam);
    } else {
#pragma unroll
        for (int u = 0; u < 8; u++) pa[u] = A[aOff + (long long)u * sak];
    }
    if (bK) {
#pragma unroll
        for (int i = 0; i < 4; i++) pb2[i] = *(const float2*)(Bp + bOff + (long long)(32 * i) * sbn);
    } else {
#pragma unroll
        for (int u = 0; u < 8; u++) pb[u] = Bp[bOff + (long long)u * sbk];
    }

    for (int k0 = 0; k0 < K; k0 += BK) {
        // ---- stage tile (regs -> smem, f16 packed) ----
        if (aK) {
#pragma unroll
            for (int i = 0; i < 4; i++)
                ((unsigned*)&As2[a_j & 3][a_mm + 32 * i])[a_j >> 2] = pack2h(pa2[i].x, pa2[i].y);
        } else {
#pragma unroll
            for (int jj = 0; jj < 4; jj++)
                ((unsigned*)&As2[jj][a_m])[selA] = pack2h(pa[2 * jj], pa[2 * jj + 1]);
        }
        if (bK) {
#pragma unroll
            for (int i = 0; i < 4; i++)
                ((unsigned*)&Bs2[b_j & 3][b_nn + 32 * i])[b_j >> 2] = pack2h(pb2[i].x, pb2[i].y);
        } else {
#pragma unroll
            for (int jj = 0; jj < 4; jj++)
                ((unsigned*)&Bs2[jj][b_n])[selB] = pack2h(pb[2 * jj], pb[2 * jj + 1]);
        }
        __syncthreads();

        // ---- prefetch next tile ----
        aOff += (long long)BK * sak;
        bOff += (long long)BK * sbk;
        if (k0 + BK < K) {
            if (aK) {
#pragma unroll
                for (int i = 0; i < 4; i++) pa2[i] = *(const float2*)(A + aOff + (long long)(32 * i) * sam);
            } else {
#pragma unroll
                for (int u = 0; u < 8; u++) pa[u] = A[aOff + (long long)u * sak];
            }
            if (bK) {
#pragma unroll
                for (int i = 0; i < 4; i++) pb2[i] = *(const float2*)(Bp + bOff + (long long)(32 * i) * sbn);
            } else {
#pragma unroll
                for (int u = 0; u < 8; u++) pb[u] = Bp[bOff + (long long)u * sbk];
            }
        }

        // ---- compute one k16 slice ----
        unsigned af[4][4], bf[4][2];
#pragma unroll
        for (int mt = 0; mt < 4; mt++) {
            float2 lo = a2p[aIdx + mt * 16];
            float2 hi = a2p[aIdx + mt * 16 + 8];
            af[mt][0] = __float_as_uint(lo.x);   // rows r,   k=2c..2c+1
            af[mt][1] = __float_as_uint(hi.x);   // rows r+8, k=2c..2c+1
            af[mt][2] = __float_as_uint(lo.y);   // rows r,   k=2c+8..2c+9
            af[mt][3] = __float_as_uint(hi.y);   // rows r+8, k=2c+8..2c+9
        }
#pragma unroll
        for (int nt = 0; nt < 4; nt++) {
            float2 pbv = b2p[bIdx + nt * 8];
            bf[nt][0] = __float_as_uint(pbv.x);
            bf[nt][1] = __float_as_uint(pbv.y);
        }
#pragma unroll
        for (int mt = 0; mt < 4; mt++)
#pragma unroll
            for (int nt = 0; nt < 4; nt++)
                mma16(acc[mt][nt], af[mt], bf[nt]);
        __syncthreads();
    }

    // ---- epilogue: bias + residual, float2 stores ----
#pragma unroll
    for (int mt = 0; mt < 4; mt++) {
        int row = m0 + wm + mt * 16 + (lane >> 2);
        float bi0 = bias ? bias[row]     : 0.f;
        float bi1 = bias ? bias[row + 8] : 0.f;
#pragma unroll
        for (int nt = 0; nt < 4; nt++) {
            int col = n0 + wn + nt * 8 + 2 * (lane & 3);
            float2 v0 = make_float2(acc[mt][nt][0] + bi0, acc[mt][nt][1] + bi0);
            float2 v1 = make_float2(acc[mt][nt][2] + bi1, acc[mt][nt][3] + bi1);
            if (res) {
                float2 r0 = *(const float2*)(res + (long long)row * N + col);
                float2 r1 = *(const float2*)(res + (long long)(row + 8) * N + col);
                v0.x += r0.x; v0.y += r0.y;
                v1.x += r1.x; v1.y += r1.y;
            }
            *(float2*)(C + (long long)row * N + col)       = v0;
            *(float2*)(C + (long long)(row + 8) * N + col) = v1;
        }
    }
}

// ---------------- orchestration ----------------
extern "C" void kernel_launch(void* const* d_in, const int* in_sizes, int n_in,
                              void* d_out, int out_size) {
    const float* content = (const float*)d_in[0];
    const float* style   = (const float*)d_in[1];
    const float* csa_w   = (const float*)d_in[2];
    const float* csa_b   = (const float*)d_in[3];
    const float* ssa_w   = (const float*)d_in[4];
    const float* ssa_b   = (const float*)d_in[5];
    const float* ca_w    = (const float*)d_in[6];
    const float* ca_b    = (const float*)d_in[7];

    float *xn, *q, *k, *v, *o, *cf, *sf, *attn;
    cudaGetSymbolAddress((void**)&xn,   g_xn);
    cudaGetSymbolAddress((void**)&q,    g_q);
    cudaGetSymbolAddress((void**)&k,    g_k);
    cudaGetSymbolAddress((void**)&v,    g_v);
    cudaGetSymbolAddress((void**)&o,    g_o);
    cudaGetSymbolAddress((void**)&cf,   g_cf);
    cudaGetSymbolAddress((void**)&sf,   g_sf);
    cudaGetSymbolAddress((void**)&attn, g_attn);

    const int B = BATCH, C = CCH, N = NSP;
    const long long CN = (long long)C * N;
    const long long NN = (long long)N * N;
    const long long WW = (long long)C * C;

    dim3 convGrid(N / 128, C / 128, B);          // (32,4,4)
    dim3 enGrid  (N / 128, N / 128, B);          // (32,32,4)
    dim3 chSplitGrid(C / 128, C / 128, B * 8);   // (4,4,32)

    // ================= content self-attention =================
    mvn_kernel<<<B * C, 256>>>(content, xn, N);
    gemm_h<<<convGrid, 256>>>(csa_w + 0 * WW, xn,      q, 0, C, 1, CN, N, 1, CN, csa_b + 0 * C, nullptr, 0, C, N, C, 1);
    gemm_h<<<convGrid, 256>>>(csa_w + 1 * WW, xn,      k, 0, C, 1, CN, N, 1, CN, csa_b + 1 * C, nullptr, 0, C, N, C, 1);
    gemm_h<<<convGrid, 256>>>(csa_w + 2 * WW, content, v, 0, C, 1, CN, N, 1, CN, csa_b + 2 * C, nullptr, 0, C, N, C, 1);
    // E[i,j] = sum_c q[c,i] k[c,j]
    gemm_h<<<enGrid, 256>>>(q, k, attn, CN, 1, N, CN, N, 1, NN, nullptr, nullptr, 0, N, N, C, 1);
    softmax_kernel<<<B * N, 256>>>(attn, N);
    // O[c,i] = sum_j v[c,j] attn[i,j]
    gemm_h<<<convGrid, 256>>>(v, attn, o, CN, N, 1, NN, 1, N, CN, nullptr, nullptr, 0, C, N, N, 1);
    gemm_h<<<convGrid, 256>>>(csa_w + 3 * WW, o, cf, 0, C, 1, CN, N, 1, CN, csa_b + 3 * C, content, CN, C, N, C, 1);

    // ================= style self-attention (channel attention) =================
    mvn_kernel<<<B * C, 256>>>(style, xn, N);
    gemm_h<<<convGrid, 256>>>(ssa_w + 0 * WW, style, q, 0, C, 1, CN, N, 1, CN, ssa_b + 0 * C, nullptr, 0, C, N, C, 1); // f
    gemm_h<<<convGrid, 256>>>(ssa_w + 1 * WW, style, k, 0, C, 1, CN, N, 1, CN, ssa_b + 1 * C, nullptr, 0, C, N, C, 1); // g
    gemm_h<<<convGrid, 256>>>(ssa_w + 2 * WW, xn,    v, 0, C, 1, CN, N, 1, CN, ssa_b + 2 * C, nullptr, 0, C, N, C, 1); // h
    // E[c,d] = sum_i f[c,i] g[d,i] — split-K x8: partials into g_o, reduce into attn
    gemm_h<<<chSplitGrid, 256>>>(q, k, o, CN, N, 1, CN, 1, N, WW, nullptr, nullptr, 0, C, C, N / 8, 8);
    reduce8_kernel<<<(int)(B * WW / 4 / 256), 256>>>(o, attn);
    softmax_kernel<<<B * C, 256>>>(attn, C);
    // O[c,i] = sum_d attn[d,c] h[d,i]
    gemm_h<<<convGrid, 256>>>(attn, v, o, WW, 1, C, CN, N, 1, CN, nullptr, nullptr, 0, C, N, C, 1);
    gemm_h<<<convGrid, 256>>>(ssa_w + 3 * WW, o, sf, 0, C, 1, CN, N, 1, CN, ssa_b + 3 * C, style, CN, C, N, C, 1);

    // ================= cross attention =================
    mvn_kernel<<<B * C, 256>>>(cf, xn, N);
    gemm_h<<<convGrid, 256>>>(ca_w + 0 * WW, xn, q, 0, C, 1, CN, N, 1, CN, ca_b + 0 * C, nullptr, 0, C, N, C, 1);
    mvn_kernel<<<B * C, 256>>>(sf, xn, N);
    gemm_h<<<convGrid, 256>>>(ca_w + 1 * WW, xn, k, 0, C, 1, CN, N, 1, CN, ca_b + 1 * C, nullptr, 0, C, N, C, 1);
    gemm_h<<<convGrid, 256>>>(ca_w + 2 * WW, sf, v, 0, C, 1, CN, N, 1, CN, ca_b + 2 * C, nullptr, 0, C, N, C, 1);
    gemm_h<<<enGrid, 256>>>(q, k, attn, CN, 1, N, CN, N, 1, NN, nullptr, nullptr, 0, N, N, C, 1);
    softmax_kernel<<<B * N, 256>>>(attn, N);
    gemm_h<<<convGrid, 256>>>(v, attn, o, CN, N, 1, NN, 1, N, CN, nullptr, nullptr, 0, C, N, N, 1);
    gemm_h<<<convGrid, 256>>>(ca_w + 3 * WW, o, (float*)d_out, 0, C, 1, CN, N, 1, CN, ca_b + 3 * C, cf, CN, C, N, C, 1);
}